// round 1
// baseline (speedup 1.0000x reference)
#include <cuda_runtime.h>
#include <math.h>

#define NB 512      // batch
#define NT 32       // timesteps
#define ND 512      // depth (feature slice)
#define NC 128      // num classes
#define NR 512      // rnn hidden
#define NG 2048     // 4*rnn
#define KX 640      // depth + ncc

// Scratch (static __device__ allowed; no cudaMalloc)
__device__ float g_Z[(size_t)NB * NT * NG];   // 128 MiB: Z[t*512+b][n] = x@kernel + bias
__device__ float g_h[2][NB * NR];             // double-buffered hidden state
__device__ float g_c[NB * NR];                // cell state (updated in place, owner-exclusive)

// ---------------------------------------------------------------------------
// init: h0 = c0 = 0
// ---------------------------------------------------------------------------
__global__ void k_init() {
    int i = blockIdx.x * blockDim.x + threadIdx.x;
    if (i < NB * NR) { g_h[0][i] = 0.f; g_c[i] = 0.f; }
}

// ---------------------------------------------------------------------------
// Precompute Z = X @ kernel + bias
//   X[m, :] for m = t*512 + b is [f_pool[b,t,:512] , (t==0 ? 0 : gt[b,t-1,:128])]
//   M=16384, K=640, N=2048.  128x128 tile, BK=16, 256 thr, 8x8 per thread.
// ---------------------------------------------------------------------------
__global__ void k_precompute(const float* __restrict__ f_pool,
                             const float* __restrict__ gt,
                             const float* __restrict__ W,
                             const float* __restrict__ bias)
{
    __shared__ float As[16][128];
    __shared__ float Bs[16][128];
    const int tid = threadIdx.x;          // 256
    const int tx = tid & 15, ty = tid >> 4;
    const int m0 = blockIdx.y * 128;
    const int n0 = blockIdx.x * 128;
    const int t  = m0 >> 9;               // 128 | 512 so t constant per block
    const int b0 = m0 & 511;

    float acc[8][8];
#pragma unroll
    for (int i = 0; i < 8; i++)
#pragma unroll
        for (int j = 0; j < 8; j++) acc[i][j] = 0.f;

    const int aIdx = tid * 2;             // float4 slot base

    for (int k0 = 0; k0 < KX; k0 += 16) {
        // ---- load A tile (gathered X), store transposed As[k][row]
#pragma unroll
        for (int l = 0; l < 2; l++) {
            int q   = aIdx + l;           // 0..511
            int row = q >> 2;             // 0..127
            int kq  = (q & 3) << 2;       // 0,4,8,12
            int k   = k0 + kq;
            float4 v;
            if (k < ND) {
                v = *(const float4*)(f_pool + ((size_t)(b0 + row) * NT + t) * ND + k);
            } else if (t == 0) {
                v = make_float4(0.f, 0.f, 0.f, 0.f);
            } else {
                v = *(const float4*)(gt + ((size_t)(b0 + row) * NT + (t - 1)) * NC + (k - ND));
            }
            As[kq + 0][row] = v.x; As[kq + 1][row] = v.y;
            As[kq + 2][row] = v.z; As[kq + 3][row] = v.w;
        }
        // ---- load B tile (kernel rows k0..k0+15, cols n0..n0+127)
#pragma unroll
        for (int l = 0; l < 2; l++) {
            int q   = aIdx + l;           // 0..511
            int row = q >> 5;             // 0..15
            int cq  = (q & 31) << 2;      // 0..124
            *(float4*)&Bs[row][cq] =
                *(const float4*)(W + (size_t)(k0 + row) * NG + n0 + cq);
        }
        __syncthreads();

#pragma unroll
        for (int k = 0; k < 16; k++) {
            float a[8], bv[8];
            *(float4*)&a[0]  = *(float4*)&As[k][ty * 4];
            *(float4*)&a[4]  = *(float4*)&As[k][64 + ty * 4];
            *(float4*)&bv[0] = *(float4*)&Bs[k][tx * 4];
            *(float4*)&bv[4] = *(float4*)&Bs[k][64 + tx * 4];
#pragma unroll
            for (int i = 0; i < 8; i++)
#pragma unroll
                for (int j = 0; j < 8; j++)
                    acc[i][j] += a[i] * bv[j];
        }
        __syncthreads();
    }

    // ---- epilogue: + bias, store Z
#pragma unroll
    for (int ih = 0; ih < 2; ih++)
#pragma unroll
    for (int ii = 0; ii < 4; ii++) {
        int m = m0 + ih * 64 + ty * 4 + ii;
        int i = ih * 4 + ii;
#pragma unroll
        for (int jh = 0; jh < 2; jh++) {
            int n = n0 + jh * 64 + tx * 4;
            float4 v;
            v.x = acc[i][jh * 4 + 0] + bias[n + 0];
            v.y = acc[i][jh * 4 + 1] + bias[n + 1];
            v.z = acc[i][jh * 4 + 2] + bias[n + 2];
            v.w = acc[i][jh * 4 + 3] + bias[n + 3];
            *(float4*)&g_Z[(size_t)m * NG + n] = v;
        }
    }
}

// ---------------------------------------------------------------------------
// One recurrence step: z = Z[t] + h @ rec_kernel ; LSTM gates ; h,c update.
// Tile: 64 batch rows x 16 j-cols x 4 gates.  Grid (32, 8), 256 threads.
// Each thread owns (4 rows) x (1 j) x (4 gates) -> local gate fusion.
// ---------------------------------------------------------------------------
__global__ void k_step(const float* __restrict__ rec, int t, int bufin)
{
    __shared__ float As[16][64];
    __shared__ float Bs[16][64];
    const int tid = threadIdx.x;          // 256
    const int tx = tid & 15, ty = tid >> 4;
    const int b0 = blockIdx.y * 64;
    const int j0 = blockIdx.x * 16;
    const float* __restrict__ h_in = g_h[bufin];
    float* __restrict__ h_out = g_h[bufin ^ 1];

    float acc[4][4];
#pragma unroll
    for (int r = 0; r < 4; r++)
#pragma unroll
        for (int g = 0; g < 4; g++) acc[r][g] = 0.f;

    for (int k0 = 0; k0 < NR; k0 += 16) {
        {   // A: h_in[b0..b0+63][k0..k0+15] transposed
            int row = tid >> 2;           // 0..63
            int kq  = (tid & 3) << 2;
            float4 v = *(const float4*)(h_in + (size_t)(b0 + row) * NR + k0 + kq);
            As[kq + 0][row] = v.x; As[kq + 1][row] = v.y;
            As[kq + 2][row] = v.z; As[kq + 3][row] = v.w;
        }
        {   // B: rec[k][g*512 + j0 + jj] packed as Bs[k][g*16+jj]
            int row = tid >> 4;           // 0..15
            int e   = (tid & 15) * 4;     // 0..60
            int g   = e >> 4;
            int jj  = e & 15;
            *(float4*)&Bs[row][e] =
                *(const float4*)(rec + (size_t)(k0 + row) * NG + g * NR + j0 + jj);
        }
        __syncthreads();

#pragma unroll
        for (int k = 0; k < 16; k++) {
            float4 a = *(float4*)&As[k][ty * 4];
            float bv[4];
#pragma unroll
            for (int g = 0; g < 4; g++) bv[g] = Bs[k][g * 16 + tx];
            float av[4] = {a.x, a.y, a.z, a.w};
#pragma unroll
            for (int r = 0; r < 4; r++)
#pragma unroll
                for (int g = 0; g < 4; g++)
                    acc[r][g] += av[r] * bv[g];
        }
        __syncthreads();
    }

    const int j = j0 + tx;
#pragma unroll
    for (int r = 0; r < 4; r++) {
        int b = b0 + ty * 4 + r;
        size_t zb = ((size_t)t * NB + b) * NG + j;
        float zi = acc[r][0] + g_Z[zb];
        float zf = acc[r][1] + g_Z[zb + NR];
        float zg = acc[r][2] + g_Z[zb + 2 * NR];
        float zo = acc[r][3] + g_Z[zb + 3 * NR];
        float si = 1.f / (1.f + expf(-zi));
        float sf = 1.f / (1.f + expf(-zf));
        float so = 1.f / (1.f + expf(-zo));
        float tg = tanhf(zg);
        int ci = b * NR + j;
        float cn = sf * g_c[ci] + si * tg;
        g_c[ci] = cn;
        h_out[ci] = so * tanhf(cn);
    }
}

// ---------------------------------------------------------------------------
// Logits + argmax + one-hot write for step t.
// Block = 16 batch rows, 128 threads (one per class). Grid = 32.
// ---------------------------------------------------------------------------
__global__ void k_logits(const float* __restrict__ sw,
                         const float* __restrict__ sb,
                         float* __restrict__ out, int t, int bufh)
{
    __shared__ float hs[16][NR];          // 32 KB
    __shared__ float lg[16][NC];          // 8 KB
    __shared__ int   amax[16];
    const int tid = threadIdx.x;          // 128
    const int b0  = blockIdx.x * 16;
    const float* __restrict__ h = g_h[bufh];

    for (int q = tid; q < 16 * (NR / 4); q += 128) {
        int r  = q / (NR / 4);
        int kq = (q % (NR / 4)) * 4;
        *(float4*)&hs[r][kq] = *(const float4*)(h + (size_t)(b0 + r) * NR + kq);
    }
    __syncthreads();

    float acc[16];
#pragma unroll
    for (int r = 0; r < 16; r++) acc[r] = 0.f;
    const int j = tid;
#pragma unroll 4
    for (int k = 0; k < NR; k++) {
        float w = sw[(size_t)k * NC + j];
#pragma unroll
        for (int r = 0; r < 16; r++) acc[r] += hs[r][k] * w;
    }
    float bj = sb[j];
#pragma unroll
    for (int r = 0; r < 16; r++) lg[r][j] = acc[r] + bj;
    __syncthreads();

    if (tid < 16) {
        float best = lg[tid][0]; int bi = 0;
        for (int c = 1; c < NC; c++) {
            float v = lg[tid][c];
            if (v > best) { best = v; bi = c; }   // first max, matches jnp.argmax
        }
        amax[tid] = bi;
    }
    __syncthreads();

#pragma unroll
    for (int r = 0; r < 16; r++) {
        int b = b0 + r;
        out[((size_t)b * NT + t) * NC + j] = (j == amax[r]) ? 1.f : 0.f;
    }
}

// ---------------------------------------------------------------------------
// Copy final h, c into output tail
// ---------------------------------------------------------------------------
__global__ void k_finalize(float* __restrict__ out, int bufh)
{
    int i = blockIdx.x * blockDim.x + threadIdx.x;
    if (i < NB * NR) {
        out[(size_t)NB * NT * NC + i]           = g_h[bufh][i];
        out[(size_t)NB * NT * NC + NB * NR + i] = g_c[i];
    }
}

// ---------------------------------------------------------------------------
extern "C" void kernel_launch(void* const* d_in, const int* in_sizes, int n_in,
                              void* d_out, int out_size)
{
    const float* f_pool = (const float*)d_in[0];
    const float* gt     = (const float*)d_in[1];
    const float* W      = (const float*)d_in[2];
    const float* rec    = (const float*)d_in[3];
    const float* bias   = (const float*)d_in[4];
    const float* sw     = (const float*)d_in[5];
    const float* sb     = (const float*)d_in[6];
    float* out = (float*)d_out;

    k_init<<<(NB * NR + 255) / 256, 256>>>();
    k_precompute<<<dim3(16, 128), 256>>>(f_pool, gt, W, bias);
    for (int t = 0; t < NT; t++) {
        k_step<<<dim3(32, 8), 256>>>(rec, t, t & 1);
        k_logits<<<32, 128>>>(sw, sb, out, t, (t + 1) & 1);
    }
    k_finalize<<<(NB * NR + 255) / 256, 256>>>(out, 0 /* = NT & 1 */);
}

// round 2
// speedup vs baseline: 1.2385x; 1.2385x over previous
#include <cuda_runtime.h>
#include <math.h>

#define NB 512      // batch
#define NT 32       // timesteps
#define ND 512      // depth (feature slice)
#define NC 128      // num classes
#define NR 512      // rnn hidden
#define NG 2048     // 4*rnn
#define KX 640      // depth + ncc

// Scratch (static __device__ allowed; no cudaMalloc)
__device__ float g_Z[(size_t)NB * NT * NG];   // 128 MiB: Z[t*512+b][n] = x@kernel + bias
__device__ float g_h[2][NB * NR];             // double-buffered hidden state
__device__ float g_c[NB * NR];                // cell state (updated in place, owner-exclusive)

// ---------------------------------------------------------------------------
// init: h0 = c0 = 0
// ---------------------------------------------------------------------------
__global__ void k_init() {
    int i = blockIdx.x * blockDim.x + threadIdx.x;
    if (i < NB * NR) { g_h[0][i] = 0.f; g_c[i] = 0.f; }
}

// ---------------------------------------------------------------------------
// Precompute Z = X @ kernel + bias
//   X[m, :] for m = t*512 + b is [f_pool[b,t,:512] , (t==0 ? 0 : gt[b,t-1,:128])]
//   M=16384, K=640, N=2048.  128x128 tile, BK=16, 256 thr, 8x8 per thread.
// ---------------------------------------------------------------------------
__global__ void k_precompute(const float* __restrict__ f_pool,
                             const float* __restrict__ gt,
                             const float* __restrict__ W,
                             const float* __restrict__ bias)
{
    __shared__ float As[16][128];
    __shared__ float Bs[16][128];
    const int tid = threadIdx.x;          // 256
    const int tx = tid & 15, ty = tid >> 4;
    const int m0 = blockIdx.y * 128;
    const int n0 = blockIdx.x * 128;
    const int t  = m0 >> 9;               // 128 | 512 so t constant per block
    const int b0 = m0 & 511;

    float acc[8][8];
#pragma unroll
    for (int i = 0; i < 8; i++)
#pragma unroll
        for (int j = 0; j < 8; j++) acc[i][j] = 0.f;

    const int aIdx = tid * 2;             // float4 slot base

    for (int k0 = 0; k0 < KX; k0 += 16) {
        // ---- load A tile (gathered X), store transposed As[k][row]
#pragma unroll
        for (int l = 0; l < 2; l++) {
            int q   = aIdx + l;           // 0..511
            int row = q >> 2;             // 0..127
            int kq  = (q & 3) << 2;       // 0,4,8,12
            int k   = k0 + kq;
            float4 v;
            if (k < ND) {
                v = *(const float4*)(f_pool + ((size_t)(b0 + row) * NT + t) * ND + k);
            } else if (t == 0) {
                v = make_float4(0.f, 0.f, 0.f, 0.f);
            } else {
                v = *(const float4*)(gt + ((size_t)(b0 + row) * NT + (t - 1)) * NC + (k - ND));
            }
            As[kq + 0][row] = v.x; As[kq + 1][row] = v.y;
            As[kq + 2][row] = v.z; As[kq + 3][row] = v.w;
        }
        // ---- load B tile (kernel rows k0..k0+15, cols n0..n0+127)
#pragma unroll
        for (int l = 0; l < 2; l++) {
            int q   = aIdx + l;           // 0..511
            int row = q >> 5;             // 0..15
            int cq  = (q & 31) << 2;      // 0..124
            *(float4*)&Bs[row][cq] =
                *(const float4*)(W + (size_t)(k0 + row) * NG + n0 + cq);
        }
        __syncthreads();

#pragma unroll
        for (int k = 0; k < 16; k++) {
            float a[8], bv[8];
            *(float4*)&a[0]  = *(float4*)&As[k][ty * 4];
            *(float4*)&a[4]  = *(float4*)&As[k][64 + ty * 4];
            *(float4*)&bv[0] = *(float4*)&Bs[k][tx * 4];
            *(float4*)&bv[4] = *(float4*)&Bs[k][64 + tx * 4];
#pragma unroll
            for (int i = 0; i < 8; i++)
#pragma unroll
                for (int j = 0; j < 8; j++)
                    acc[i][j] += a[i] * bv[j];
        }
        __syncthreads();
    }

    // ---- epilogue: + bias, store Z
#pragma unroll
    for (int ih = 0; ih < 2; ih++)
#pragma unroll
    for (int ii = 0; ii < 4; ii++) {
        int m = m0 + ih * 64 + ty * 4 + ii;
        int i = ih * 4 + ii;
#pragma unroll
        for (int jh = 0; jh < 2; jh++) {
            int n = n0 + jh * 64 + tx * 4;
            float4 v;
            v.x = acc[i][jh * 4 + 0] + bias[n + 0];
            v.y = acc[i][jh * 4 + 1] + bias[n + 1];
            v.z = acc[i][jh * 4 + 2] + bias[n + 2];
            v.w = acc[i][jh * 4 + 3] + bias[n + 3];
            *(float4*)&g_Z[(size_t)m * NG + n] = v;
        }
    }
}

// ---------------------------------------------------------------------------
// One recurrence step: z = Z[t] + h @ rec_kernel ; LSTM gates ; h,c update.
// Tile: 64 batch rows x 16 j-cols x 4 gates.  Grid (32, 8), 256 threads.
// ---------------------------------------------------------------------------
__global__ void k_step(const float* __restrict__ rec, int t, int bufin)
{
    __shared__ float As[16][64];
    __shared__ float Bs[16][64];
    const int tid = threadIdx.x;          // 256
    const int tx = tid & 15, ty = tid >> 4;
    const int b0 = blockIdx.y * 64;
    const int j0 = blockIdx.x * 16;
    const float* __restrict__ h_in = g_h[bufin];
    float* __restrict__ h_out = g_h[bufin ^ 1];

    float acc[4][4];
#pragma unroll
    for (int r = 0; r < 4; r++)
#pragma unroll
        for (int g = 0; g < 4; g++) acc[r][g] = 0.f;

    for (int k0 = 0; k0 < NR; k0 += 16) {
        {   // A: h_in[b0..b0+63][k0..k0+15] transposed
            int row = tid >> 2;           // 0..63
            int kq  = (tid & 3) << 2;
            float4 v = *(const float4*)(h_in + (size_t)(b0 + row) * NR + k0 + kq);
            As[kq + 0][row] = v.x; As[kq + 1][row] = v.y;
            As[kq + 2][row] = v.z; As[kq + 3][row] = v.w;
        }
        {   // B: rec[k][g*512 + j0 + jj] packed as Bs[k][g*16+jj]
            int row = tid >> 4;           // 0..15
            int e   = (tid & 15) * 4;     // 0..60
            int g   = e >> 4;
            int jj  = e & 15;
            *(float4*)&Bs[row][e] =
                *(const float4*)(rec + (size_t)(k0 + row) * NG + g * NR + j0 + jj);
        }
        __syncthreads();

#pragma unroll
        for (int k = 0; k < 16; k++) {
            float4 a = *(float4*)&As[k][ty * 4];
            float bv[4];
#pragma unroll
            for (int g = 0; g < 4; g++) bv[g] = Bs[k][g * 16 + tx];
            float av[4] = {a.x, a.y, a.z, a.w};
#pragma unroll
            for (int r = 0; r < 4; r++)
#pragma unroll
                for (int g = 0; g < 4; g++)
                    acc[r][g] += av[r] * bv[g];
        }
        __syncthreads();
    }

    const int j = j0 + tx;
#pragma unroll
    for (int r = 0; r < 4; r++) {
        int b = b0 + ty * 4 + r;
        size_t zb = ((size_t)t * NB + b) * NG + j;
        float zi = acc[r][0] + g_Z[zb];
        float zf = acc[r][1] + g_Z[zb + NR];
        float zg = acc[r][2] + g_Z[zb + 2 * NR];
        float zo = acc[r][3] + g_Z[zb + 3 * NR];
        float si = 1.f / (1.f + expf(-zi));
        float sf = 1.f / (1.f + expf(-zf));
        float so = 1.f / (1.f + expf(-zo));
        float tg = tanhf(zg);
        int ci = b * NR + j;
        float cn = sf * g_c[ci] + si * tg;
        g_c[ci] = cn;
        h_out[ci] = so * tanhf(cn);
    }
}

// ---------------------------------------------------------------------------
// Logits + argmax + one-hot for step t.  REWRITTEN:
// grid = 128 blocks (4 batch rows each), 256 threads.
// thread = (class j = tid&127, k-half kh = tid>>7). k-loop unrolled x8.
// Smem reduce halves, warp-shuffle argmax (first-max tie rule), coalesced
// one-hot stores.
// ---------------------------------------------------------------------------
__global__ void __launch_bounds__(256) k_logits(
    const float* __restrict__ sw,
    const float* __restrict__ sb,
    float* __restrict__ out, int t, int bufh)
{
    __shared__ float hs[4][NR];           // 8 KB
    __shared__ float part[4][NC];         // 2 KB (kh=1 partials)
    __shared__ float lg[4][NC];           // 2 KB
    __shared__ int   amax[4];
    const int tid = threadIdx.x;          // 256
    const int j   = tid & 127;
    const int kh  = tid >> 7;             // 0/1
    const int b0  = blockIdx.x * 4;
    const float* __restrict__ h = g_h[bufh];

    // stage 4 contiguous h rows (2048 floats) into smem: 2 float4 per thread
    {
        const float4* src = (const float4*)(h + (size_t)b0 * NR);
        float4* dst = (float4*)&hs[0][0];
        dst[tid]       = src[tid];
        dst[tid + 256] = src[tid + 256];
    }
    __syncthreads();

    float a0 = 0.f, a1 = 0.f, a2 = 0.f, a3 = 0.f;
    const int kbase = kh << 8;
#pragma unroll 8
    for (int kk = 0; kk < 256; kk++) {
        int k = kbase + kk;
        float w = sw[(size_t)k * NC + j];
        a0 += hs[0][k] * w;
        a1 += hs[1][k] * w;
        a2 += hs[2][k] * w;
        a3 += hs[3][k] * w;
    }
    if (kh) {
        part[0][j] = a0; part[1][j] = a1; part[2][j] = a2; part[3][j] = a3;
    }
    __syncthreads();
    if (!kh) {
        float bj = sb[j];
        lg[0][j] = a0 + part[0][j] + bj;
        lg[1][j] = a1 + part[1][j] + bj;
        lg[2][j] = a2 + part[2][j] + bj;
        lg[3][j] = a3 + part[3][j] + bj;
    }
    __syncthreads();

    // argmax: warp w handles row w (w<4). lane scans 4 ascending classes
    // (strict > keeps first max), then shuffle-reduce with tie -> lower idx.
    const int wid = tid >> 5, lane = tid & 31;
    if (wid < 4) {
        float best = -INFINITY; int bi = 0;
        int cbase = lane * 4;
#pragma unroll
        for (int cc = 0; cc < 4; cc++) {
            float v = lg[wid][cbase + cc];
            if (v > best) { best = v; bi = cbase + cc; }
        }
#pragma unroll
        for (int off = 16; off; off >>= 1) {
            float ov = __shfl_down_sync(0xffffffffu, best, off);
            int   oi = __shfl_down_sync(0xffffffffu, bi,   off);
            if (ov > best || (ov == best && oi < bi)) { best = ov; bi = oi; }
        }
        if (lane == 0) amax[wid] = bi;
    }
    __syncthreads();

    // one-hot stores: thread group kh covers rows {2kh, 2kh+1}
#pragma unroll
    for (int rr = 0; rr < 2; rr++) {
        int r = kh * 2 + rr;
        out[((size_t)(b0 + r) * NT + t) * NC + j] = (j == amax[r]) ? 1.f : 0.f;
    }
}

// ---------------------------------------------------------------------------
// Copy final h, c into output tail
// ---------------------------------------------------------------------------
__global__ void k_finalize(float* __restrict__ out, int bufh)
{
    int i = blockIdx.x * blockDim.x + threadIdx.x;
    if (i < NB * NR) {
        out[(size_t)NB * NT * NC + i]           = g_h[bufh][i];
        out[(size_t)NB * NT * NC + NB * NR + i] = g_c[i];
    }
}

// ---------------------------------------------------------------------------
extern "C" void kernel_launch(void* const* d_in, const int* in_sizes, int n_in,
                              void* d_out, int out_size)
{
    const float* f_pool = (const float*)d_in[0];
    const float* gt     = (const float*)d_in[1];
    const float* W      = (const float*)d_in[2];
    const float* rec    = (const float*)d_in[3];
    const float* bias   = (const float*)d_in[4];
    const float* sw     = (const float*)d_in[5];
    const float* sb     = (const float*)d_in[6];
    float* out = (float*)d_out;

    k_init<<<(NB * NR + 255) / 256, 256>>>();
    k_precompute<<<dim3(16, 128), 256>>>(f_pool, gt, W, bias);
    for (int t = 0; t < NT; t++) {
        k_step<<<dim3(32, 8), 256>>>(rec, t, t & 1);
        k_logits<<<128, 256>>>(sw, sb, out, t, (t + 1) & 1);
    }
    k_finalize<<<(NB * NR + 255) / 256, 256>>>(out, 0 /* = NT & 1 */);
}

// round 3
// speedup vs baseline: 1.4516x; 1.1721x over previous
#include <cuda_runtime.h>
#include <math.h>

#define NB 512      // batch
#define NT 32       // timesteps
#define ND 512      // depth (feature slice)
#define NC 128      // num classes
#define NR 512      // rnn hidden
#define NG 2048     // 4*rnn
#define KX 640      // depth + ncc

// Scratch (static __device__ allowed; no cudaMalloc)
__device__ float g_Z[(size_t)NB * NT * NG];   // 128 MiB
__device__ float g_h[2][NB * NR];             // double-buffered hidden state
__device__ float g_c[NB * NR];                // cell state

// ---------------------------------------------------------------------------
// packed f32x2 helpers (sm_100+)
// ---------------------------------------------------------------------------
__device__ __forceinline__ unsigned long long pack2(float x, float y) {
    unsigned long long r;
    asm("mov.b64 %0, {%1, %2};" : "=l"(r) : "f"(x), "f"(y));
    return r;
}
__device__ __forceinline__ void unpack2(unsigned long long v, float& x, float& y) {
    asm("mov.b64 {%0, %1}, %2;" : "=f"(x), "=f"(y) : "l"(v));
}
__device__ __forceinline__ void ffma2(unsigned long long& d,
                                      unsigned long long a,
                                      unsigned long long b) {
    asm("fma.rn.f32x2 %0, %1, %2, %0;" : "+l"(d) : "l"(a), "l"(b));
}

// ---------------------------------------------------------------------------
__global__ void k_init() {
    int i = blockIdx.x * blockDim.x + threadIdx.x;
    if (i < NB * NR) { g_h[0][i] = 0.f; g_c[i] = 0.f; }
}

// ---------------------------------------------------------------------------
// Precompute Z = X @ kernel + bias    (M=16384, K=640, N=2048)
// 128x128 tile, BK=16, 256 thr, 8 rows x 8 cols (4 j-pairs) per thread, FFMA2.
// ---------------------------------------------------------------------------
__global__ void __launch_bounds__(256, 2) k_precompute(
    const float* __restrict__ f_pool,
    const float* __restrict__ gt,
    const float* __restrict__ W,
    const float* __restrict__ bias)
{
    __shared__ float As[16][128];
    __shared__ float Bs[16][128];
    const int tid = threadIdx.x;
    const int tx = tid & 15, ty = tid >> 4;
    const int m0 = blockIdx.y * 128;
    const int n0 = blockIdx.x * 128;
    const int t  = m0 >> 9;
    const int b0 = m0 & 511;

    unsigned long long acc[8][4];
#pragma unroll
    for (int i = 0; i < 8; i++)
#pragma unroll
        for (int p = 0; p < 4; p++) acc[i][p] = 0ull;

    const int aIdx = tid * 2;

    for (int k0 = 0; k0 < KX; k0 += 16) {
#pragma unroll
        for (int l = 0; l < 2; l++) {
            int q   = aIdx + l;
            int row = q >> 2;
            int kq  = (q & 3) << 2;
            int k   = k0 + kq;
            float4 v;
            if (k < ND) {
                v = *(const float4*)(f_pool + ((size_t)(b0 + row) * NT + t) * ND + k);
            } else if (t == 0) {
                v = make_float4(0.f, 0.f, 0.f, 0.f);
            } else {
                v = *(const float4*)(gt + ((size_t)(b0 + row) * NT + (t - 1)) * NC + (k - ND));
            }
            As[kq + 0][row] = v.x; As[kq + 1][row] = v.y;
            As[kq + 2][row] = v.z; As[kq + 3][row] = v.w;
        }
#pragma unroll
        for (int l = 0; l < 2; l++) {
            int q   = aIdx + l;
            int row = q >> 5;
            int cq  = (q & 31) << 2;
            *(float4*)&Bs[row][cq] =
                *(const float4*)(W + (size_t)(k0 + row) * NG + n0 + cq);
        }
        __syncthreads();

#pragma unroll
        for (int k = 0; k < 16; k++) {
            float a[8];
            *(float4*)&a[0] = *(float4*)&As[k][ty * 4];
            *(float4*)&a[4] = *(float4*)&As[k][64 + ty * 4];
            unsigned long long bp[4];
            bp[0] = *(const unsigned long long*)&Bs[k][tx * 4];
            bp[1] = *(const unsigned long long*)&Bs[k][tx * 4 + 2];
            bp[2] = *(const unsigned long long*)&Bs[k][64 + tx * 4];
            bp[3] = *(const unsigned long long*)&Bs[k][64 + tx * 4 + 2];
            unsigned long long ad[8];
#pragma unroll
            for (int i = 0; i < 8; i++) ad[i] = pack2(a[i], a[i]);
#pragma unroll
            for (int i = 0; i < 8; i++)
#pragma unroll
                for (int p = 0; p < 4; p++)
                    ffma2(acc[i][p], ad[i], bp[p]);
        }
        __syncthreads();
    }

    // epilogue: + bias, store Z (pairs p=0,1 -> 4 consecutive cols; p=2,3 -> +64)
#pragma unroll
    for (int ih = 0; ih < 2; ih++)
#pragma unroll
    for (int ii = 0; ii < 4; ii++) {
        int m = m0 + ih * 64 + ty * 4 + ii;
        int i = ih * 4 + ii;
#pragma unroll
        for (int jh = 0; jh < 2; jh++) {
            int n = n0 + jh * 64 + tx * 4;
            float4 v;
            unpack2(acc[i][jh * 2 + 0], v.x, v.y);
            unpack2(acc[i][jh * 2 + 1], v.z, v.w);
            v.x += bias[n + 0]; v.y += bias[n + 1];
            v.z += bias[n + 2]; v.w += bias[n + 3];
            *(float4*)&g_Z[(size_t)m * NG + n] = v;
        }
    }
}

// ---------------------------------------------------------------------------
// One recurrence step: z = Z[t] + h @ rec_kernel ; LSTM gates ; h,c update.
// Tile: 64 b x 32 j x 4 gates. Grid (16, 8) = 128 blocks, 256 threads.
// Thread: 4 rows x 4 gates x (1 j-pair) -> 16 FFMA2 per k.
// ---------------------------------------------------------------------------
__global__ void __launch_bounds__(256) k_step(const float* __restrict__ rec,
                                              int t, int bufin)
{
    __shared__ float As[16][64];
    __shared__ float Bs[16][128];
    const int tid = threadIdx.x;
    const int tx = tid & 15, ty = tid >> 4;
    const int b0 = blockIdx.y * 64;
    const int j0 = blockIdx.x * 32;
    const float* __restrict__ h_in = g_h[bufin];
    float* __restrict__ h_out = g_h[bufin ^ 1];

    unsigned long long acc[4][4];
#pragma unroll
    for (int r = 0; r < 4; r++)
#pragma unroll
        for (int g = 0; g < 4; g++) acc[r][g] = 0ull;

    for (int k0 = 0; k0 < NR; k0 += 16) {
        {   // A: h_in[b0..b0+63][k0..k0+15] transposed -> As[k][row]
            int row = tid >> 2;
            int kq  = (tid & 3) << 2;
            float4 v = *(const float4*)(h_in + (size_t)(b0 + row) * NR + k0 + kq);
            As[kq + 0][row] = v.x; As[kq + 1][row] = v.y;
            As[kq + 2][row] = v.z; As[kq + 3][row] = v.w;
        }
        {   // B: Bs[k][g*32 + jj] <- rec[(k0+k)*NG + g*NR + j0 + jj]
#pragma unroll
            for (int l = 0; l < 2; l++) {
                int q   = tid * 2 + l;        // 0..511
                int row = q >> 5;             // 0..15
                int e   = (q & 31) << 2;      // 0..124
                int g   = e >> 5;
                int jj  = e & 31;
                *(float4*)&Bs[row][e] =
                    *(const float4*)(rec + (size_t)(k0 + row) * NG + g * NR + j0 + jj);
            }
        }
        __syncthreads();

#pragma unroll
        for (int k = 0; k < 16; k++) {
            float4 a = *(float4*)&As[k][ty * 4];
            unsigned long long bp[4];
#pragma unroll
            for (int g = 0; g < 4; g++)
                bp[g] = *(const unsigned long long*)&Bs[k][g * 32 + tx * 2];
            unsigned long long ad[4];
            ad[0] = pack2(a.x, a.x); ad[1] = pack2(a.y, a.y);
            ad[2] = pack2(a.z, a.z); ad[3] = pack2(a.w, a.w);
#pragma unroll
            for (int r = 0; r < 4; r++)
#pragma unroll
                for (int g = 0; g < 4; g++)
                    ffma2(acc[r][g], ad[r], bp[g]);
        }
        __syncthreads();
    }

    const int j = j0 + tx * 2;
#pragma unroll
    for (int r = 0; r < 4; r++) {
        int b = b0 + ty * 4 + r;
        size_t zb = ((size_t)t * NB + b) * NG + j;
        float2 zi = *(const float2*)&g_Z[zb];
        float2 zf = *(const float2*)&g_Z[zb + NR];
        float2 zg = *(const float2*)&g_Z[zb + 2 * NR];
        float2 zo = *(const float2*)&g_Z[zb + 3 * NR];
        float ai0, ai1, af0, af1, ag0, ag1, ao0, ao1;
        unpack2(acc[r][0], ai0, ai1);
        unpack2(acc[r][1], af0, af1);
        unpack2(acc[r][2], ag0, ag1);
        unpack2(acc[r][3], ao0, ao1);
        int ci = b * NR + j;
        float2 cold = *(const float2*)&g_c[ci];
        float2 cn, hn;
        {
            float vi = zi.x + ai0, vf = zf.x + af0, vg = zg.x + ag0, vo = zo.x + ao0;
            float si = 1.f / (1.f + expf(-vi));
            float sf = 1.f / (1.f + expf(-vf));
            float so = 1.f / (1.f + expf(-vo));
            float tg = tanhf(vg);
            cn.x = sf * cold.x + si * tg;
            hn.x = so * tanhf(cn.x);
        }
        {
            float vi = zi.y + ai1, vf = zf.y + af1, vg = zg.y + ag1, vo = zo.y + ao1;
            float si = 1.f / (1.f + expf(-vi));
            float sf = 1.f / (1.f + expf(-vf));
            float so = 1.f / (1.f + expf(-vo));
            float tg = tanhf(vg);
            cn.y = sf * cold.y + si * tg;
            hn.y = so * tanhf(cn.y);
        }
        *(float2*)&g_c[ci] = cn;
        *(float2*)&h_out[ci] = hn;
    }
}

// ---------------------------------------------------------------------------
// Logits + argmax + one-hot for step t.
// Grid 64 blocks (8 rows each), 512 threads: j = tid&127, kq = tid>>7 (4-way
// k split, 128 iters). h staged as row-paired float2 -> broadcast LDS.64,
// FFMA2. Smem cross-kq reduce, warp argmax (first-max tie rule).
// ---------------------------------------------------------------------------
__global__ void __launch_bounds__(512) k_logits(
    const float* __restrict__ sw,
    const float* __restrict__ sb,
    float* __restrict__ out, int t, int bufh)
{
    __shared__ float2 hsp[4][NR];         // 16 KB: hsp[p][k] = {h[2p][k], h[2p+1][k]}
    __shared__ float2 part[3][4][NC];     // 12 KB
    __shared__ float  lgs[8][NC];         // 4 KB
    __shared__ int    amax[8];
    const int tid = threadIdx.x;          // 512
    const int j   = tid & 127;
    const int kq  = tid >> 7;             // 0..3
    const int b0  = blockIdx.x * 8;
    const float* __restrict__ h = g_h[bufh];

    // stage 8 rows transposed into paired layout; coalesced global reads
#pragma unroll
    for (int r = 0; r < 8; r++) {
        float v = h[(size_t)(b0 + r) * NR + tid];
        ((float*)&hsp[r >> 1][tid])[r & 1] = v;
    }
    __syncthreads();

    unsigned long long acc[4] = {0ull, 0ull, 0ull, 0ull};
    const int kbase = kq << 7;
#pragma unroll 8
    for (int kk = 0; kk < 128; kk++) {
        int k = kbase + kk;
        float w = sw[(size_t)k * NC + j];
        unsigned long long wd = pack2(w, w);
#pragma unroll
        for (int p = 0; p < 4; p++)
            ffma2(acc[p], wd, *(const unsigned long long*)&hsp[p][k]);
    }
    if (kq) {
#pragma unroll
        for (int p = 0; p < 4; p++) {
            float x, y; unpack2(acc[p], x, y);
            part[kq - 1][p][j] = make_float2(x, y);
        }
    }
    __syncthreads();
    if (!kq) {
        float bj = sb[j];
#pragma unroll
        for (int p = 0; p < 4; p++) {
            float x, y; unpack2(acc[p], x, y);
            float2 p0 = part[0][p][j], p1 = part[1][p][j], p2 = part[2][p][j];
            lgs[2 * p + 0][j] = x + p0.x + p1.x + p2.x + bj;
            lgs[2 * p + 1][j] = y + p0.y + p1.y + p2.y + bj;
        }
    }
    __syncthreads();

    // argmax: warp w (w<8) handles row w; lane scans 4 ascending classes.
    const int wid = tid >> 5, lane = tid & 31;
    if (wid < 8) {
        float best = -INFINITY; int bi = 0;
        int cbase = lane * 4;
#pragma unroll
        for (int cc = 0; cc < 4; cc++) {
            float v = lgs[wid][cbase + cc];
            if (v > best) { best = v; bi = cbase + cc; }
        }
#pragma unroll
        for (int off = 16; off; off >>= 1) {
            float ov = __shfl_down_sync(0xffffffffu, best, off);
            int   oi = __shfl_down_sync(0xffffffffu, bi,   off);
            if (ov > best || (ov == best && oi < bi)) { best = ov; bi = oi; }
        }
        if (lane == 0) amax[wid] = bi;
    }
    __syncthreads();

    // one-hot: 8 rows x 128 cols, 2 rows per thread-group
#pragma unroll
    for (int rr = 0; rr < 2; rr++) {
        int r = kq + rr * 4;
        out[((size_t)(b0 + r) * NT + t) * NC + j] = (j == amax[r]) ? 1.f : 0.f;
    }
}

// ---------------------------------------------------------------------------
__global__ void k_finalize(float* __restrict__ out, int bufh)
{
    int i = blockIdx.x * blockDim.x + threadIdx.x;
    if (i < NB * NR) {
        out[(size_t)NB * NT * NC + i]           = g_h[bufh][i];
        out[(size_t)NB * NT * NC + NB * NR + i] = g_c[i];
    }
}

// ---------------------------------------------------------------------------
extern "C" void kernel_launch(void* const* d_in, const int* in_sizes, int n_in,
                              void* d_out, int out_size)
{
    const float* f_pool = (const float*)d_in[0];
    const float* gt     = (const float*)d_in[1];
    const float* W      = (const float*)d_in[2];
    const float* rec    = (const float*)d_in[3];
    const float* bias   = (const float*)d_in[4];
    const float* sw     = (const float*)d_in[5];
    const float* sb     = (const float*)d_in[6];
    float* out = (float*)d_out;

    k_init<<<(NB * NR + 255) / 256, 256>>>();
    k_precompute<<<dim3(16, 128), 256>>>(f_pool, gt, W, bias);
    for (int t = 0; t < NT; t++) {
        k_step<<<dim3(16, 8), 256>>>(rec, t, t & 1);
        k_logits<<<64, 512>>>(sw, sb, out, t, (t + 1) & 1);
    }
    k_finalize<<<(NB * NR + 255) / 256, 256>>>(out, 0);
}